// round 12
// baseline (speedup 1.0000x reference)
#include <cuda_runtime.h>
#include <cuda_bf16.h>
#include <cstdint>

#define N_NODES 50000
#define N_EDGES 600000
#define D_FEAT  128
#define OUT_DIM 128
#define K_DIM   256

#define SCAN_BLK 512
#define N_SCAN_BLKS ((N_NODES + SCAN_BLK - 1) / SCAN_BLK)   // 98

// ---------------------------------------------------------------------------
// Scratch (static device globals)
// ---------------------------------------------------------------------------
__device__ int g_cnt_i [N_NODES];
__device__ int g_off   [N_NODES];
__device__ int g_btot  [N_SCAN_BLKS];
__device__ int g_rank  [N_EDGES];    // rank of edge within its segment
__device__ int g_eid   [N_EDGES];    // edge ids sorted by destination node
__device__ __align__(16) float g_agg[N_NODES * D_FEAT];   // 25.6 MB

// ---------------------------------------------------------------------------
// Kernel 1: zero counters
// ---------------------------------------------------------------------------
__global__ void zero_counters_kernel() {
    int i = blockIdx.x * blockDim.x + threadIdx.x;
    if (i < N_NODES) g_cnt_i[i] = 0;
}

// ---------------------------------------------------------------------------
// Kernel 2: histogram + per-edge rank in ONE atomic pass
// ---------------------------------------------------------------------------
__global__ void count_rank_kernel(const int* __restrict__ src_idx) {
    int e = blockIdx.x * blockDim.x + threadIdx.x;
    if (e < N_EDGES) g_rank[e] = atomicAdd(&g_cnt_i[src_idx[e]], 1);
}

// ---------------------------------------------------------------------------
// Kernel 3: per-block exclusive scan; block totals to g_btot
// ---------------------------------------------------------------------------
__global__ __launch_bounds__(SCAN_BLK)
void scan_partial_kernel() {
    __shared__ int sh[SCAN_BLK];
    const int tid = threadIdx.x;
    const int i   = blockIdx.x * SCAN_BLK + tid;
    const int v   = (i < N_NODES) ? g_cnt_i[i] : 0;
    sh[tid] = v;
    __syncthreads();
    #pragma unroll
    for (int d = 1; d < SCAN_BLK; d <<= 1) {
        int t = (tid >= d) ? sh[tid - d] : 0;
        __syncthreads();
        sh[tid] += t;
        __syncthreads();
    }
    if (i < N_NODES) g_off[i] = sh[tid] - v;
    if (tid == SCAN_BLK - 1) g_btot[blockIdx.x] = sh[tid];
}

// ---------------------------------------------------------------------------
// Inline 98-element exclusive prefix of g_btot (~200 cyc). All threads join.
// ---------------------------------------------------------------------------
__device__ __forceinline__ void boff_scan(int* sb) {
    const int tid = threadIdx.x;
    int v = 0;
    if (tid < 128) {
        v = (tid < N_SCAN_BLKS) ? g_btot[tid] : 0;
        sb[tid] = v;
    }
    __syncthreads();
    #pragma unroll
    for (int d = 1; d < 128; d <<= 1) {
        int x = (tid < 128 && tid >= d) ? sb[tid - d] : 0;
        __syncthreads();
        if (tid < 128) sb[tid] += x;
        __syncthreads();
    }
    if (tid < 128) sb[tid] -= v;   // exclusive
    __syncthreads();
}

// ---------------------------------------------------------------------------
// Kernel 4: scatter edge ids — atomic-free (rank precomputed)
// ---------------------------------------------------------------------------
__global__ __launch_bounds__(256)
void scatter_ids_kernel(const int* __restrict__ src_idx) {
    __shared__ int sb[128];
    boff_scan(sb);
    int e = blockIdx.x * blockDim.x + threadIdx.x;
    if (e < N_EDGES) {
        const int s = src_idx[e];
        g_eid[g_off[s] + sb[s >> 9] + g_rank[e]] = e;
    }
}

// ---------------------------------------------------------------------------
// Kernel 5: gather-reduce. One warp per node; lane owns a float4 chunk.
// ---------------------------------------------------------------------------
__global__ __launch_bounds__(256)
void gather_kernel(const float* __restrict__ nbr_feat) {
    __shared__ int sb[128];
    boff_scan(sb);

    const int warp = (blockIdx.x * blockDim.x + threadIdx.x) >> 5;
    const int lane = threadIdx.x & 31;
    if (warp >= N_NODES) return;

    const int base = g_off[warp] + sb[warp >> 9];
    const int deg  = g_cnt_i[warp];

    const float4* nb4 = reinterpret_cast<const float4*>(nbr_feat);
    float4 acc = make_float4(0.f, 0.f, 0.f, 0.f);

    int i = 0;
    for (; i + 4 <= deg; i += 4) {
        const int e0 = g_eid[base + i];
        const int e1 = g_eid[base + i + 1];
        const int e2 = g_eid[base + i + 2];
        const int e3 = g_eid[base + i + 3];
        const float4 v0 = nb4[(size_t)e0 * (D_FEAT / 4) + lane];
        const float4 v1 = nb4[(size_t)e1 * (D_FEAT / 4) + lane];
        const float4 v2 = nb4[(size_t)e2 * (D_FEAT / 4) + lane];
        const float4 v3 = nb4[(size_t)e3 * (D_FEAT / 4) + lane];
        acc.x += (v0.x + v1.x) + (v2.x + v3.x);
        acc.y += (v0.y + v1.y) + (v2.y + v3.y);
        acc.z += (v0.z + v1.z) + (v2.z + v3.z);
        acc.w += (v0.w + v1.w) + (v2.w + v3.w);
    }
    for (; i < deg; ++i) {
        const int e = g_eid[base + i];
        const float4 v = nb4[(size_t)e * (D_FEAT / 4) + lane];
        acc.x += v.x; acc.y += v.y; acc.z += v.z; acc.w += v.w;
    }

    const float s = (deg > 0) ? (1.0f / (float)deg) : 0.0f;
    acc.x *= s; acc.y *= s; acc.z *= s; acc.w *= s;
    reinterpret_cast<float4*>(g_agg)[(size_t)warp * (D_FEAT / 4) + lane] = acc;
}

// ---------------------------------------------------------------------------
// Kernel 6: fused concat + GEMM. R10 phase structure (K halves, smem 96KB,
// 2 CTAs/SM) but re-tiled to 4 rows x 8 cols per thread so each x-dup feeds
// 4 FFMA2 (was 2) and W loads are LDS.128:
//   per 2k per warp: 4 LDS.128 (W) + 4 LDS.64 (X) + 16 MOV + 32 FFMA2
//   = 56 issue slots / 32 FFMA2  (R10: 76; R11's smem-dup variant: MIO-bound).
// launch_bounds (256,2) = 128-reg budget (NEVER lower: (256,4) spilled, +50us).
// ---------------------------------------------------------------------------
#define BM   64
#define TPB  256
#define KH   128
#define GEMM_SMEM ((KH * OUT_DIM + BM * KH) * 4)    // 65536 + 32768 = 98304 B

__global__ __launch_bounds__(TPB, 2)
void gemm_kernel(const float* __restrict__ self_feat,
                 const float* __restrict__ W,
                 float*       __restrict__ out) {
    extern __shared__ float sh[];
    float* Wsh = sh;                 // [KH][OUT_DIM]
    float* Xsh = sh + KH * OUT_DIM;  // [BM][KH]

    const int tid = threadIdx.x;
    const int n0  = blockIdx.x * BM;

    const int j0 = (tid & 15) * 8;   // output column base (0..120)
    const int r0 = (tid >> 4) * 4;   // row base within tile (0..60)

    unsigned long long acc[4][4];
    #pragma unroll
    for (int r = 0; r < 4; ++r)
        #pragma unroll
        for (int c = 0; c < 4; ++c) acc[r][c] = 0ull;

    #pragma unroll
    for (int half = 0; half < 2; ++half) {
        const float* xsrc = (half == 0) ? self_feat : g_agg;

        if (half == 1) __syncthreads();

        // Load W half (4096 float4)
        {
            const float4* W4 = reinterpret_cast<const float4*>(W + half * KH * OUT_DIM);
            float4* Wsh4 = reinterpret_cast<float4*>(Wsh);
            #pragma unroll
            for (int i = tid; i < KH * OUT_DIM / 4; i += TPB) Wsh4[i] = W4[i];
        }
        // Load X half (rows n0..n0+63)
        {
            const float4* x4 = reinterpret_cast<const float4*>(xsrc);
            const float4  z  = make_float4(0.f, 0.f, 0.f, 0.f);
            #pragma unroll
            for (int i = tid; i < BM * (KH / 4); i += TPB) {
                const int r  = i / (KH / 4);
                const int c4 = i % (KH / 4);
                const int n  = n0 + r;
                float4 v = z;
                if (n < N_NODES) v = x4[(size_t)n * (D_FEAT / 4) + c4];
                reinterpret_cast<float4*>(&Xsh[r * KH])[c4] = v;
            }
        }
        __syncthreads();

        #pragma unroll 2
        for (int k = 0; k < KH; k += 2) {
            // W row k: cols j0..j0+7 as two u64x2 (LDS.128 each)
            const ulonglong2 wa0 =
                *reinterpret_cast<const ulonglong2*>(&Wsh[k * OUT_DIM + j0]);
            const ulonglong2 wb0 =
                *reinterpret_cast<const ulonglong2*>(&Wsh[k * OUT_DIM + j0 + 4]);
            const ulonglong2 wa1 =
                *reinterpret_cast<const ulonglong2*>(&Wsh[(k + 1) * OUT_DIM + j0]);
            const ulonglong2 wb1 =
                *reinterpret_cast<const ulonglong2*>(&Wsh[(k + 1) * OUT_DIM + j0 + 4]);

            #pragma unroll
            for (int r = 0; r < 4; ++r) {
                const float2 x = *reinterpret_cast<const float2*>(&Xsh[(r0 + r) * KH + k]);
                unsigned long long xx0, xx1;
                asm("mov.b64 %0, {%1, %1};" : "=l"(xx0) : "f"(x.x));
                asm("mov.b64 %0, {%1, %1};" : "=l"(xx1) : "f"(x.y));
                asm("fma.rn.f32x2 %0, %1, %2, %0;" : "+l"(acc[r][0]) : "l"(xx0), "l"(wa0.x));
                asm("fma.rn.f32x2 %0, %1, %2, %0;" : "+l"(acc[r][1]) : "l"(xx0), "l"(wa0.y));
                asm("fma.rn.f32x2 %0, %1, %2, %0;" : "+l"(acc[r][2]) : "l"(xx0), "l"(wb0.x));
                asm("fma.rn.f32x2 %0, %1, %2, %0;" : "+l"(acc[r][3]) : "l"(xx0), "l"(wb0.y));
                asm("fma.rn.f32x2 %0, %1, %2, %0;" : "+l"(acc[r][0]) : "l"(xx1), "l"(wa1.x));
                asm("fma.rn.f32x2 %0, %1, %2, %0;" : "+l"(acc[r][1]) : "l"(xx1), "l"(wa1.y));
                asm("fma.rn.f32x2 %0, %1, %2, %0;" : "+l"(acc[r][2]) : "l"(xx1), "l"(wb1.x));
                asm("fma.rn.f32x2 %0, %1, %2, %0;" : "+l"(acc[r][3]) : "l"(xx1), "l"(wb1.y));
            }
        }
    }

    #pragma unroll
    for (int r = 0; r < 4; ++r) {
        const int n = n0 + r0 + r;
        if (n < N_NODES) {
            float o0, o1, o2, o3, o4, o5, o6, o7;
            asm("mov.b64 {%0, %1}, %2;" : "=f"(o0), "=f"(o1) : "l"(acc[r][0]));
            asm("mov.b64 {%0, %1}, %2;" : "=f"(o2), "=f"(o3) : "l"(acc[r][1]));
            asm("mov.b64 {%0, %1}, %2;" : "=f"(o4), "=f"(o5) : "l"(acc[r][2]));
            asm("mov.b64 {%0, %1}, %2;" : "=f"(o6), "=f"(o7) : "l"(acc[r][3]));
            float* po = out + (size_t)n * OUT_DIM + j0;
            *reinterpret_cast<float4*>(po)     = make_float4(o0, o1, o2, o3);
            *reinterpret_cast<float4*>(po + 4) = make_float4(o4, o5, o6, o7);
        }
    }
}

// ---------------------------------------------------------------------------
// Launch — 6 kernels, strictly serial (overlap attempts R7-R9 all lost to
// SM-residency contention).
// ---------------------------------------------------------------------------
extern "C" void kernel_launch(void* const* d_in, const int* in_sizes, int n_in,
                              void* d_out, int out_size) {
    const float* self_feat = (const float*)d_in[0];
    const float* nbr_feat  = (const float*)d_in[1];
    const int*   src_idx   = (const int*)  d_in[2];
    const float* W         = (const float*)d_in[3];
    float*       out       = (float*)d_out;

    (void)in_sizes; (void)n_in; (void)out_size;

    const int nodes_blks = (N_NODES + 255) / 256;
    const int edges_blks = (N_EDGES + 255) / 256;

    zero_counters_kernel<<<nodes_blks, 256>>>();           // 1
    count_rank_kernel<<<edges_blks, 256>>>(src_idx);       // 2
    scan_partial_kernel<<<N_SCAN_BLKS, SCAN_BLK>>>();      // 3
    scatter_ids_kernel<<<edges_blks, 256>>>(src_idx);      // 4
    gather_kernel<<<(N_NODES + 7) / 8, 256>>>(nbr_feat);   // 5

    cudaFuncSetAttribute(gemm_kernel,
                         cudaFuncAttributeMaxDynamicSharedMemorySize, GEMM_SMEM);
    gemm_kernel<<<(N_NODES + BM - 1) / BM, TPB, GEMM_SMEM>>>(self_feat, W, out);  // 6
}

// round 13
// speedup vs baseline: 1.2590x; 1.2590x over previous
#include <cuda_runtime.h>
#include <cuda_bf16.h>
#include <cstdint>

#define N_NODES 50000
#define N_EDGES 600000
#define D_FEAT  128
#define OUT_DIM 128
#define K_DIM   256

#define SCAN_BLK 512
#define N_SCAN_BLKS ((N_NODES + SCAN_BLK - 1) / SCAN_BLK)   // 98

// ---------------------------------------------------------------------------
// Scratch (static device globals) — g_agg is GONE (gather fused into GEMM)
// ---------------------------------------------------------------------------
__device__ int g_cnt_i [N_NODES];
__device__ int g_off   [N_NODES];
__device__ int g_btot  [N_SCAN_BLKS];
__device__ int g_rank  [N_EDGES];    // rank of edge within its segment
__device__ int g_eid   [N_EDGES];    // edge ids sorted by destination node

// ---------------------------------------------------------------------------
// Kernel 1: zero counters
// ---------------------------------------------------------------------------
__global__ void zero_counters_kernel() {
    int i = blockIdx.x * blockDim.x + threadIdx.x;
    if (i < N_NODES) g_cnt_i[i] = 0;
}

// ---------------------------------------------------------------------------
// Kernel 2: histogram + per-edge rank in ONE atomic pass
// ---------------------------------------------------------------------------
__global__ void count_rank_kernel(const int* __restrict__ src_idx) {
    int e = blockIdx.x * blockDim.x + threadIdx.x;
    if (e < N_EDGES) g_rank[e] = atomicAdd(&g_cnt_i[src_idx[e]], 1);
}

// ---------------------------------------------------------------------------
// Kernel 3: per-block exclusive scan; block totals to g_btot
// ---------------------------------------------------------------------------
__global__ __launch_bounds__(SCAN_BLK)
void scan_partial_kernel() {
    __shared__ int sh[SCAN_BLK];
    const int tid = threadIdx.x;
    const int i   = blockIdx.x * SCAN_BLK + tid;
    const int v   = (i < N_NODES) ? g_cnt_i[i] : 0;
    sh[tid] = v;
    __syncthreads();
    #pragma unroll
    for (int d = 1; d < SCAN_BLK; d <<= 1) {
        int t = (tid >= d) ? sh[tid - d] : 0;
        __syncthreads();
        sh[tid] += t;
        __syncthreads();
    }
    if (i < N_NODES) g_off[i] = sh[tid] - v;
    if (tid == SCAN_BLK - 1) g_btot[blockIdx.x] = sh[tid];
}

// ---------------------------------------------------------------------------
// Inline 98-element exclusive prefix of g_btot (~200 cyc). All threads join.
// ---------------------------------------------------------------------------
__device__ __forceinline__ void boff_scan(int* sb) {
    const int tid = threadIdx.x;
    int v = 0;
    if (tid < 128) {
        v = (tid < N_SCAN_BLKS) ? g_btot[tid] : 0;
        sb[tid] = v;
    }
    __syncthreads();
    #pragma unroll
    for (int d = 1; d < 128; d <<= 1) {
        int x = (tid < 128 && tid >= d) ? sb[tid - d] : 0;
        __syncthreads();
        if (tid < 128) sb[tid] += x;
        __syncthreads();
    }
    if (tid < 128) sb[tid] -= v;   // exclusive
    __syncthreads();
}

// ---------------------------------------------------------------------------
// Kernel 4: scatter edge ids — atomic-free (rank precomputed)
// ---------------------------------------------------------------------------
__global__ __launch_bounds__(256)
void scatter_ids_kernel(const int* __restrict__ src_idx) {
    __shared__ int sb[128];
    boff_scan(sb);
    int e = blockIdx.x * blockDim.x + threadIdx.x;
    if (e < N_EDGES) {
        const int s = src_idx[e];
        g_eid[g_off[s] + sb[s >> 9] + g_rank[e]] = e;
    }
}

// ---------------------------------------------------------------------------
// Kernel 5: fused gather + concat + GEMM.
// R10's proven GEMM skeleton (K halves, smem 96KB, 2 CTAs/SM, 8x4 thread tile,
// fma.rn.f32x2), but half 1's X tile is GATHERED DIRECTLY from nbr_feat
// (one warp per node row, lane owns a float4 chunk, MLP-4) instead of read
// from a precomputed g_agg. Kills 51MB of DRAM traffic + one launch, and the
// 2 desynced CTAs/SM overlap gather-DRAM with FMA naturally.
// launch_bounds (256,2) = 128-reg budget (NEVER lower: (256,4) spilled, +50us).
// ---------------------------------------------------------------------------
#define BM   64
#define TPB  256
#define KH   128
#define GEMM_SMEM ((KH * OUT_DIM + BM * KH) * 4)    // 65536 + 32768 = 98304 B

__global__ __launch_bounds__(TPB, 2)
void gemm_fused_kernel(const float* __restrict__ self_feat,
                       const float* __restrict__ nbr_feat,
                       const float* __restrict__ W,
                       float*       __restrict__ out) {
    extern __shared__ float sh[];
    __shared__ int sb[128];
    float* Wsh = sh;                 // [KH][OUT_DIM]
    float* Xsh = sh + KH * OUT_DIM;  // [BM][KH]

    const int tid = threadIdx.x;
    const int n0  = blockIdx.x * BM;

    boff_scan(sb);   // needed by the half-1 gather fill

    const int j0 = (tid & 31) * 4;   // output column base
    const int r0 = (tid >> 5) * 8;   // row base within tile

    unsigned long long a01[8], a23[8];
    #pragma unroll
    for (int r = 0; r < 8; ++r) { a01[r] = 0ull; a23[r] = 0ull; }

    #pragma unroll
    for (int half = 0; half < 2; ++half) {
        if (half == 1) __syncthreads();

        // Load W half (4096 float4)
        {
            const float4* W4 = reinterpret_cast<const float4*>(W + half * KH * OUT_DIM);
            float4* Wsh4 = reinterpret_cast<float4*>(Wsh);
            #pragma unroll
            for (int i = tid; i < KH * OUT_DIM / 4; i += TPB) Wsh4[i] = W4[i];
        }

        if (half == 0) {
            // X = self_feat tile (coalesced)
            const float4* x4 = reinterpret_cast<const float4*>(self_feat);
            const float4  z  = make_float4(0.f, 0.f, 0.f, 0.f);
            #pragma unroll
            for (int i = tid; i < BM * (KH / 4); i += TPB) {
                const int r  = i / (KH / 4);
                const int c4 = i % (KH / 4);
                const int n  = n0 + r;
                float4 v = z;
                if (n < N_NODES) v = x4[(size_t)n * (D_FEAT / 4) + c4];
                reinterpret_cast<float4*>(&Xsh[r * KH])[c4] = v;
            }
        } else {
            // X = segment mean, gathered in place. Warp w handles rows w, w+8,...
            const int wid  = tid >> 5;
            const int lane = tid & 31;
            const float4* nb4 = reinterpret_cast<const float4*>(nbr_feat);
            for (int r = wid; r < BM; r += 8) {
                const int node = n0 + r;
                float4 acc = make_float4(0.f, 0.f, 0.f, 0.f);
                if (node < N_NODES) {
                    const int base = g_off[node] + sb[node >> 9];
                    const int deg  = g_cnt_i[node];
                    int i = 0;
                    for (; i + 4 <= deg; i += 4) {      // 4 rows in flight
                        const int e0 = g_eid[base + i];
                        const int e1 = g_eid[base + i + 1];
                        const int e2 = g_eid[base + i + 2];
                        const int e3 = g_eid[base + i + 3];
                        const float4 v0 = nb4[(size_t)e0 * (D_FEAT / 4) + lane];
                        const float4 v1 = nb4[(size_t)e1 * (D_FEAT / 4) + lane];
                        const float4 v2 = nb4[(size_t)e2 * (D_FEAT / 4) + lane];
                        const float4 v3 = nb4[(size_t)e3 * (D_FEAT / 4) + lane];
                        acc.x += (v0.x + v1.x) + (v2.x + v3.x);
                        acc.y += (v0.y + v1.y) + (v2.y + v3.y);
                        acc.z += (v0.z + v1.z) + (v2.z + v3.z);
                        acc.w += (v0.w + v1.w) + (v2.w + v3.w);
                    }
                    for (; i < deg; ++i) {
                        const int e = g_eid[base + i];
                        const float4 v = nb4[(size_t)e * (D_FEAT / 4) + lane];
                        acc.x += v.x; acc.y += v.y; acc.z += v.z; acc.w += v.w;
                    }
                    const float s = (deg > 0) ? (1.0f / (float)deg) : 0.0f;
                    acc.x *= s; acc.y *= s; acc.z *= s; acc.w *= s;
                }
                reinterpret_cast<float4*>(&Xsh[r * KH])[lane] = acc;
            }
        }
        __syncthreads();

        #pragma unroll 2
        for (int k = 0; k < KH; k += 2) {
            const unsigned long long wA0 =
                *reinterpret_cast<const unsigned long long*>(&Wsh[k * OUT_DIM + j0]);
            const unsigned long long wB0 =
                *reinterpret_cast<const unsigned long long*>(&Wsh[k * OUT_DIM + j0 + 2]);
            const unsigned long long wA1 =
                *reinterpret_cast<const unsigned long long*>(&Wsh[(k + 1) * OUT_DIM + j0]);
            const unsigned long long wB1 =
                *reinterpret_cast<const unsigned long long*>(&Wsh[(k + 1) * OUT_DIM + j0 + 2]);

            #pragma unroll
            for (int r = 0; r < 8; ++r) {
                const float2 x = *reinterpret_cast<const float2*>(&Xsh[(r0 + r) * KH + k]);
                unsigned long long xx0, xx1;
                asm("mov.b64 %0, {%1, %1};" : "=l"(xx0) : "f"(x.x));
                asm("mov.b64 %0, {%1, %1};" : "=l"(xx1) : "f"(x.y));
                asm("fma.rn.f32x2 %0, %1, %2, %0;" : "+l"(a01[r]) : "l"(xx0), "l"(wA0));
                asm("fma.rn.f32x2 %0, %1, %2, %0;" : "+l"(a23[r]) : "l"(xx0), "l"(wB0));
                asm("fma.rn.f32x2 %0, %1, %2, %0;" : "+l"(a01[r]) : "l"(xx1), "l"(wA1));
                asm("fma.rn.f32x2 %0, %1, %2, %0;" : "+l"(a23[r]) : "l"(xx1), "l"(wB1));
            }
        }
    }

    #pragma unroll
    for (int r = 0; r < 8; ++r) {
        const int n = n0 + r0 + r;
        if (n < N_NODES) {
            float o0, o1, o2, o3;
            asm("mov.b64 {%0, %1}, %2;" : "=f"(o0), "=f"(o1) : "l"(a01[r]));
            asm("mov.b64 {%0, %1}, %2;" : "=f"(o2), "=f"(o3) : "l"(a23[r]));
            *reinterpret_cast<float4*>(&out[(size_t)n * OUT_DIM + j0]) =
                make_float4(o0, o1, o2, o3);
        }
    }
}

// ---------------------------------------------------------------------------
// Launch — 5 kernels, serial
// ---------------------------------------------------------------------------
extern "C" void kernel_launch(void* const* d_in, const int* in_sizes, int n_in,
                              void* d_out, int out_size) {
    const float* self_feat = (const float*)d_in[0];
    const float* nbr_feat  = (const float*)d_in[1];
    const int*   src_idx   = (const int*)  d_in[2];
    const float* W         = (const float*)d_in[3];
    float*       out       = (float*)d_out;

    (void)in_sizes; (void)n_in; (void)out_size;

    const int nodes_blks = (N_NODES + 255) / 256;
    const int edges_blks = (N_EDGES + 255) / 256;

    zero_counters_kernel<<<nodes_blks, 256>>>();           // 1
    count_rank_kernel<<<edges_blks, 256>>>(src_idx);       // 2
    scan_partial_kernel<<<N_SCAN_BLKS, SCAN_BLK>>>();      // 3
    scatter_ids_kernel<<<edges_blks, 256>>>(src_idx);      // 4

    cudaFuncSetAttribute(gemm_fused_kernel,
                         cudaFuncAttributeMaxDynamicSharedMemorySize, GEMM_SMEM);
    gemm_fused_kernel<<<(N_NODES + BM - 1) / BM, TPB, GEMM_SMEM>>>(
        self_feat, nbr_feat, W, out);                      // 5
}

// round 14
// speedup vs baseline: 1.3040x; 1.0357x over previous
#include <cuda_runtime.h>
#include <cuda_bf16.h>
#include <cstdint>

#define N_NODES 50000
#define N_EDGES 600000
#define D_FEAT  128
#define OUT_DIM 128
#define K_DIM   256

#define SCAN_BLK 512
#define N_SCAN_BLKS ((N_NODES + SCAN_BLK - 1) / SCAN_BLK)   // 98

// ---------------------------------------------------------------------------
// Scratch (static device globals)
// ---------------------------------------------------------------------------
__device__ int g_cnt_i [N_NODES];
__device__ int g_off   [N_NODES];
__device__ int g_btot  [N_SCAN_BLKS];
__device__ __align__(16) int g_rank[N_EDGES];   // rank of edge within segment
__device__ int g_eid   [N_EDGES];               // edge ids sorted by dest node
__device__ __align__(16) float g_agg[N_NODES * D_FEAT];   // 25.6 MB

// ---------------------------------------------------------------------------
// Kernel 1: zero counters
// ---------------------------------------------------------------------------
__global__ void zero_counters_kernel() {
    int i = blockIdx.x * blockDim.x + threadIdx.x;
    if (i < N_NODES) g_cnt_i[i] = 0;
}

// ---------------------------------------------------------------------------
// Kernel 2: histogram + per-edge rank, 4 edges per thread (4 independent
// atomics in flight; was MLP=1 and latency-bound at 10us).
// N_EDGES % 4 == 0.
// ---------------------------------------------------------------------------
__global__ void count_rank_kernel(const int* __restrict__ src_idx) {
    const int t = blockIdx.x * blockDim.x + threadIdx.x;
    const int e = t * 4;
    if (e >= N_EDGES) return;
    const int4 s = *reinterpret_cast<const int4*>(src_idx + e);
    int4 r;
    r.x = atomicAdd(&g_cnt_i[s.x], 1);
    r.y = atomicAdd(&g_cnt_i[s.y], 1);
    r.z = atomicAdd(&g_cnt_i[s.z], 1);
    r.w = atomicAdd(&g_cnt_i[s.w], 1);
    *reinterpret_cast<int4*>(g_rank + e) = r;
}

// ---------------------------------------------------------------------------
// Kernel 3: per-block exclusive scan — warp-shuffle version (2 barriers
// instead of 18; was 5us latency-bound).
// ---------------------------------------------------------------------------
__global__ __launch_bounds__(SCAN_BLK)
void scan_partial_kernel() {
    __shared__ int wtot[16];
    const int tid  = threadIdx.x;
    const int lane = tid & 31;
    const int wid  = tid >> 5;
    const int i    = blockIdx.x * SCAN_BLK + tid;
    const int v    = (i < N_NODES) ? g_cnt_i[i] : 0;

    // inclusive warp scan
    int x = v;
    #pragma unroll
    for (int d = 1; d < 32; d <<= 1) {
        int y = __shfl_up_sync(0xffffffffu, x, d);
        if (lane >= d) x += y;
    }
    if (lane == 31) wtot[wid] = x;
    __syncthreads();

    // warp 0 scans the 16 warp totals (exclusive)
    if (wid == 0) {
        int w = (lane < 16) ? wtot[lane] : 0;
        int ws = w;
        #pragma unroll
        for (int d = 1; d < 16; d <<= 1) {
            int y = __shfl_up_sync(0xffffffffu, ws, d);
            if (lane >= d) ws += y;
        }
        if (lane < 16) wtot[lane] = ws - w;   // exclusive
    }
    __syncthreads();

    const int incl = x + wtot[wid];
    if (i < N_NODES) g_off[i] = incl - v;     // exclusive within block
    if (tid == SCAN_BLK - 1) g_btot[blockIdx.x] = incl;
}

// ---------------------------------------------------------------------------
// Inline 98-element exclusive prefix of g_btot (~200 cyc). All threads join.
// ---------------------------------------------------------------------------
__device__ __forceinline__ void boff_scan(int* sb) {
    const int tid = threadIdx.x;
    int v = 0;
    if (tid < 128) {
        v = (tid < N_SCAN_BLKS) ? g_btot[tid] : 0;
        sb[tid] = v;
    }
    __syncthreads();
    #pragma unroll
    for (int d = 1; d < 128; d <<= 1) {
        int x = (tid < 128 && tid >= d) ? sb[tid - d] : 0;
        __syncthreads();
        if (tid < 128) sb[tid] += x;
        __syncthreads();
    }
    if (tid < 128) sb[tid] -= v;   // exclusive
    __syncthreads();
}

// ---------------------------------------------------------------------------
// Kernel 4: scatter edge ids — atomic-free, 4 edges per thread (4 independent
// off-load/store chains; was MLP=1 and latency-bound at 11us).
// ---------------------------------------------------------------------------
__global__ __launch_bounds__(256)
void scatter_ids_kernel(const int* __restrict__ src_idx) {
    __shared__ int sb[128];
    boff_scan(sb);
    const int t = blockIdx.x * blockDim.x + threadIdx.x;
    const int e = t * 4;
    if (e >= N_EDGES) return;
    const int4 s = *reinterpret_cast<const int4*>(src_idx + e);
    const int4 r = *reinterpret_cast<const int4*>(g_rank + e);
    const int p0 = g_off[s.x] + sb[s.x >> 9] + r.x;
    const int p1 = g_off[s.y] + sb[s.y >> 9] + r.y;
    const int p2 = g_off[s.z] + sb[s.z >> 9] + r.z;
    const int p3 = g_off[s.w] + sb[s.w >> 9] + r.w;
    g_eid[p0] = e;
    g_eid[p1] = e + 1;
    g_eid[p2] = e + 2;
    g_eid[p3] = e + 3;
}

// ---------------------------------------------------------------------------
// Kernel 5: gather-reduce (R10-proven). One warp per node; lane owns a
// float4 chunk; 4 edge rows in flight.
// ---------------------------------------------------------------------------
__global__ __launch_bounds__(256)
void gather_kernel(const float* __restrict__ nbr_feat) {
    __shared__ int sb[128];
    boff_scan(sb);

    const int warp = (blockIdx.x * blockDim.x + threadIdx.x) >> 5;
    const int lane = threadIdx.x & 31;
    if (warp >= N_NODES) return;

    const int base = g_off[warp] + sb[warp >> 9];
    const int deg  = g_cnt_i[warp];

    const float4* nb4 = reinterpret_cast<const float4*>(nbr_feat);
    float4 acc = make_float4(0.f, 0.f, 0.f, 0.f);

    int i = 0;
    for (; i + 4 <= deg; i += 4) {
        const int e0 = g_eid[base + i];
        const int e1 = g_eid[base + i + 1];
        const int e2 = g_eid[base + i + 2];
        const int e3 = g_eid[base + i + 3];
        const float4 v0 = nb4[(size_t)e0 * (D_FEAT / 4) + lane];
        const float4 v1 = nb4[(size_t)e1 * (D_FEAT / 4) + lane];
        const float4 v2 = nb4[(size_t)e2 * (D_FEAT / 4) + lane];
        const float4 v3 = nb4[(size_t)e3 * (D_FEAT / 4) + lane];
        acc.x += (v0.x + v1.x) + (v2.x + v3.x);
        acc.y += (v0.y + v1.y) + (v2.y + v3.y);
        acc.z += (v0.z + v1.z) + (v2.z + v3.z);
        acc.w += (v0.w + v1.w) + (v2.w + v3.w);
    }
    for (; i < deg; ++i) {
        const int e = g_eid[base + i];
        const float4 v = nb4[(size_t)e * (D_FEAT / 4) + lane];
        acc.x += v.x; acc.y += v.y; acc.z += v.z; acc.w += v.w;
    }

    const float s = (deg > 0) ? (1.0f / (float)deg) : 0.0f;
    acc.x *= s; acc.y *= s; acc.z *= s; acc.w *= s;
    reinterpret_cast<float4*>(g_agg)[(size_t)warp * (D_FEAT / 4) + lane] = acc;
}

// ---------------------------------------------------------------------------
// Kernel 6: fused concat + GEMM (R10-proven; do NOT touch the inner loop —
// the smem-dup (R11) and 4x8-retile (R12) variants both regressed).
// K halves, smem 96KB, 2 CTAs/SM, 8x4 thread tile, fma.rn.f32x2.
// launch_bounds (256,2) = 128-reg budget (NEVER lower: (256,4) spilled, +50us).
// ---------------------------------------------------------------------------
#define BM   64
#define TPB  256
#define KH   128
#define GEMM_SMEM ((KH * OUT_DIM + BM * KH) * 4)    // 98304 B

__global__ __launch_bounds__(TPB, 2)
void gemm_kernel(const float* __restrict__ self_feat,
                 const float* __restrict__ W,
                 float*       __restrict__ out) {
    extern __shared__ float sh[];
    float* Wsh = sh;                 // [KH][OUT_DIM]
    float* Xsh = sh + KH * OUT_DIM;  // [BM][KH]

    const int tid = threadIdx.x;
    const int n0  = blockIdx.x * BM;

    const int j0 = (tid & 31) * 4;
    const int r0 = (tid >> 5) * 8;

    unsigned long long a01[8], a23[8];
    #pragma unroll
    for (int r = 0; r < 8; ++r) { a01[r] = 0ull; a23[r] = 0ull; }

    #pragma unroll
    for (int half = 0; half < 2; ++half) {
        const float* xsrc = (half == 0) ? self_feat : g_agg;

        if (half == 1) __syncthreads();

        {
            const float4* W4 = reinterpret_cast<const float4*>(W + half * KH * OUT_DIM);
            float4* Wsh4 = reinterpret_cast<float4*>(Wsh);
            #pragma unroll
            for (int i = tid; i < KH * OUT_DIM / 4; i += TPB) Wsh4[i] = W4[i];
        }
        {
            const float4* x4 = reinterpret_cast<const float4*>(xsrc);
            const float4  z  = make_float4(0.f, 0.f, 0.f, 0.f);
            #pragma unroll
            for (int i = tid; i < BM * (KH / 4); i += TPB) {
                const int r  = i / (KH / 4);
                const int c4 = i % (KH / 4);
                const int n  = n0 + r;
                float4 v = z;
                if (n < N_NODES) v = x4[(size_t)n * (D_FEAT / 4) + c4];
                reinterpret_cast<float4*>(&Xsh[r * KH])[c4] = v;
            }
        }
        __syncthreads();

        #pragma unroll 2
        for (int k = 0; k < KH; k += 2) {
            const unsigned long long wA0 =
                *reinterpret_cast<const unsigned long long*>(&Wsh[k * OUT_DIM + j0]);
            const unsigned long long wB0 =
                *reinterpret_cast<const unsigned long long*>(&Wsh[k * OUT_DIM + j0 + 2]);
            const unsigned long long wA1 =
                *reinterpret_cast<const unsigned long long*>(&Wsh[(k + 1) * OUT_DIM + j0]);
            const unsigned long long wB1 =
                *reinterpret_cast<const unsigned long long*>(&Wsh[(k + 1) * OUT_DIM + j0 + 2]);

            #pragma unroll
            for (int r = 0; r < 8; ++r) {
                const float2 x = *reinterpret_cast<const float2*>(&Xsh[(r0 + r) * KH + k]);
                unsigned long long xx0, xx1;
                asm("mov.b64 %0, {%1, %1};" : "=l"(xx0) : "f"(x.x));
                asm("mov.b64 %0, {%1, %1};" : "=l"(xx1) : "f"(x.y));
                asm("fma.rn.f32x2 %0, %1, %2, %0;" : "+l"(a01[r]) : "l"(xx0), "l"(wA0));
                asm("fma.rn.f32x2 %0, %1, %2, %0;" : "+l"(a23[r]) : "l"(xx0), "l"(wB0));
                asm("fma.rn.f32x2 %0, %1, %2, %0;" : "+l"(a01[r]) : "l"(xx1), "l"(wA1));
                asm("fma.rn.f32x2 %0, %1, %2, %0;" : "+l"(a23[r]) : "l"(xx1), "l"(wB1));
            }
        }
    }

    #pragma unroll
    for (int r = 0; r < 8; ++r) {
        const int n = n0 + r0 + r;
        if (n < N_NODES) {
            float o0, o1, o2, o3;
            asm("mov.b64 {%0, %1}, %2;" : "=f"(o0), "=f"(o1) : "l"(a01[r]));
            asm("mov.b64 {%0, %1}, %2;" : "=f"(o2), "=f"(o3) : "l"(a23[r]));
            *reinterpret_cast<float4*>(&out[(size_t)n * OUT_DIM + j0]) =
                make_float4(o0, o1, o2, o3);
        }
    }
}

// ---------------------------------------------------------------------------
// Launch — 6 kernels, strictly serial (all fusion/overlap variants R7-R9,
// R13 regressed: each phase needs its own occupancy envelope).
// ---------------------------------------------------------------------------
extern "C" void kernel_launch(void* const* d_in, const int* in_sizes, int n_in,
                              void* d_out, int out_size) {
    const float* self_feat = (const float*)d_in[0];
    const float* nbr_feat  = (const float*)d_in[1];
    const int*   src_idx   = (const int*)  d_in[2];
    const float* W         = (const float*)d_in[3];
    float*       out       = (float*)d_out;

    (void)in_sizes; (void)n_in; (void)out_size;

    const int nodes_blks = (N_NODES + 255) / 256;
    const int e4_blks    = (N_EDGES / 4 + 255) / 256;

    zero_counters_kernel<<<nodes_blks, 256>>>();           // 1
    count_rank_kernel<<<e4_blks, 256>>>(src_idx);          // 2
    scan_partial_kernel<<<N_SCAN_BLKS, SCAN_BLK>>>();      // 3
    scatter_ids_kernel<<<e4_blks, 256>>>(src_idx);         // 4
    gather_kernel<<<(N_NODES + 7) / 8, 256>>>(nbr_feat);   // 5

    cudaFuncSetAttribute(gemm_kernel,
                         cudaFuncAttributeMaxDynamicSharedMemorySize, GEMM_SMEM);
    gemm_kernel<<<(N_NODES + BM - 1) / BM, TPB, GEMM_SMEM>>>(self_feat, W, out);  // 6
}